// round 2
// baseline (speedup 1.0000x reference)
#include <cuda_runtime.h>

#define HH 512
#define WW 512
#define BC 6
#define NPIX (HH * WW)

// ---- static device scratch (no runtime allocation allowed) ----
__device__ float g_gmag[BC * NPIX];
__device__ float g_xnA[BC * NPIX];
__device__ float g_ynA[BC * NPIX];
__device__ float g_xnB[BC * NPIX];
__device__ float g_ynB[BC * NPIX];
__device__ int    g_imgmax[BC];
__device__ int    g_gmax[BC];
__device__ double g_sum[BC];
__device__ double g_sumsq[BC];
__device__ float  g_mean[BC];
__device__ float  g_invstd[BC];

__device__ __forceinline__ int refl(int i, int n) {
    // jnp.pad mode="reflect": no edge repeat; radius<=2 so single reflection suffices
    if (i < 0) i = -i;
    if (i >= n) i = 2 * (n - 1) - i;
    return i;
}

// -------------------- init --------------------
__global__ void k_init() {
    int i = threadIdx.x;
    if (i < BC) {
        g_imgmax[i] = 0;     // inputs are >= 0, so 0-int is a valid float max identity
        g_gmax[i]   = 0;
        g_sum[i]    = 0.0;
        g_sumsq[i]  = 0.0;
    }
}

// -------------------- per-channel max of img --------------------
__global__ void k_imgmax(const float* __restrict__ img) {
    int c = blockIdx.y;
    const float* p = img + c * NPIX;
    float m = 0.f;
    for (int i = blockIdx.x * blockDim.x + threadIdx.x; i < NPIX;
         i += gridDim.x * blockDim.x)
        m = fmaxf(m, p[i]);
    __shared__ float sm[8];
    int lane = threadIdx.x & 31, warp = threadIdx.x >> 5;
#pragma unroll
    for (int o = 16; o; o >>= 1) m = fmaxf(m, __shfl_xor_sync(0xffffffffu, m, o));
    if (lane == 0) sm[warp] = m;
    __syncthreads();
    if (threadIdx.x == 0) {
#pragma unroll
        for (int i = 1; i < 8; i++) m = fmaxf(m, sm[i]);
        atomicMax(&g_imgmax[c], __float_as_int(m));  // nonneg floats: int cmp valid
    }
}

// -------------------- Sobel + rotate + gmag max --------------------
__global__ void k_sobel(const float* __restrict__ img) {
    int c = blockIdx.z;
    const float* p = img + c * NPIX;
    int x = blockIdx.x * 32 + threadIdx.x;
    int y = blockIdx.y * 8 + threadIdx.y;
    float maxv = __int_as_float(g_imgmax[c]);
    float inv = 1.0f / maxv;

    float a[3][3];
#pragma unroll
    for (int j = 0; j < 3; j++)
#pragma unroll
        for (int i = 0; i < 3; i++) {
            int yy = y + j - 1, xx = x + i - 1;
            a[j][i] = ((unsigned)yy < HH && (unsigned)xx < WW) ? p[yy * WW + xx] : 0.f;
        }
    // classic Sobel, cross-correlation, zero padding
    float gx = (a[0][2] - a[0][0]) + 2.f * (a[1][2] - a[1][0]) + (a[2][2] - a[2][0]);
    float gy = (a[2][0] - a[0][0]) + 2.f * (a[2][1] - a[0][1]) + (a[2][2] - a[0][2]);
    gx = fmaxf(gx * inv, 1e-12f);
    gy = fmaxf(gy * inv, 1e-12f);

    float gm = sqrtf(fmaf(gx, gx, gy * gy));
    float invg = 1.0f / gm;
    float x0 = gx * invg, y0 = gy * invg;
    // rotation by fp32(pi/2): cos = -4.3711388e-8, sin = 1.0 (fp32-exact values)
    const float ct = -4.3711388e-08f, st = 1.0f;
    float xn = x0 * ct - y0 * st;
    float yn = y0 * ct + x0 * st;

    int o = c * NPIX + y * WW + x;
    g_gmag[o] = gm;
    g_xnA[o]  = xn;
    g_ynA[o]  = yn;

    // block max of gm -> atomic
    __shared__ float sm[8];
    int tid = threadIdx.y * 32 + threadIdx.x;
    int lane = tid & 31, warp = tid >> 5;
    float m = gm;
#pragma unroll
    for (int off = 16; off; off >>= 1) m = fmaxf(m, __shfl_xor_sync(0xffffffffu, m, off));
    if (lane == 0) sm[warp] = m;
    __syncthreads();
    if (tid == 0) {
#pragma unroll
        for (int i = 1; i < 8; i++) m = fmaxf(m, sm[i]);
        atomicMax(&g_gmax[c], __float_as_int(m));
    }
}

// -------------------- ETF iteration --------------------
// sel==0: read A write B ; sel==1: read B write A
__global__ void k_iter(int sel) {
    __shared__ float sg[36][36];
    __shared__ float sx[36][36];
    __shared__ float sy[36][36];

    int c = blockIdx.z;
    const float* gm = g_gmag + c * NPIX;
    const float* xi = (sel ? g_xnB : g_xnA) + c * NPIX;
    const float* yi = (sel ? g_ynB : g_ynA) + c * NPIX;
    float* xo = (sel ? g_xnA : g_xnB) + c * NPIX;
    float* yo = (sel ? g_ynA : g_ynB) + c * NPIX;

    float ginv = 1.0f / __int_as_float(g_gmax[c]);

    int bx0 = blockIdx.x * 32 - 2;
    int by0 = blockIdx.y * 32 - 2;
    int tid = threadIdx.y * 32 + threadIdx.x;

    for (int i = tid; i < 36 * 36; i += 256) {
        int ly = i / 36, lx = i - ly * 36;
        int gy = refl(by0 + ly, HH);
        int gx = refl(bx0 + lx, WW);
        int o = gy * WW + gx;
        sg[ly][lx] = gm[o] * ginv;   // gnorm
        sx[ly][lx] = xi[o];
        sy[ly][lx] = yi[o];
    }
    __syncthreads();

    int px = blockIdx.x * 32 + threadIdx.x;
    int tx = threadIdx.x;
#pragma unroll
    for (int k = 0; k < 4; k++) {
        int ly = threadIdx.y + k * 8;
        int py = blockIdx.y * 32 + ly;
        float xc = sx[ly + 2][tx + 2];
        float yc = sy[ly + 2][tx + 2];
        float gc = sg[ly + 2][tx + 2];
        float xr = 0.f, yr = 0.f;
#pragma unroll
        for (int dy = 0; dy < 5; dy++) {
#pragma unroll
            for (int dx = 0; dx < 5; dx++) {
                float gn  = sg[ly + dy][tx + dx];
                float xnb = sx[ly + dy][tx + dx];
                float ynb = sy[ly + dy][tx + dx];
                float d   = gn - gc;
                // Wm = 0.5*(1+tanh(d)) == 1/(1+exp(-2d))
                float wm  = __fdividef(1.0f, 1.0f + __expf(-2.0f * d));
                float dot = fmaf(xc, xnb, yc * ynb);
                float t   = gn * (wm * dot);
                xr = fmaf(xnb, t, xr);
                yr = fmaf(ynb, t, yr);
            }
        }
        float invm = rsqrtf(fmaf(xr, xr, yr * yr));
        int o = py * WW + px;
        xo[o] = xr * invm;
        yo[o] = yr * invm;
    }
}

// -------------------- angle + per-channel sum/sumsq --------------------
__global__ void k_angle(float* __restrict__ out) {
    int c = blockIdx.y;
    int i = blockIdx.x * blockDim.x + threadIdx.x;
    int o = c * NPIX + i;
    float xn = g_xnB[o], yn = g_ynB[o];
    float ang = atanf(-yn / xn);
    float a = (180.0f * ang) / 3.14159274101257324f;
    out[o] = a;

    double s  = (double)a;
    double s2 = (double)a * (double)a;
    __shared__ double ss[8], sq[8];
    int lane = threadIdx.x & 31, warp = threadIdx.x >> 5;
#pragma unroll
    for (int off = 16; off; off >>= 1) {
        s  += __shfl_xor_sync(0xffffffffu, s, off);
        s2 += __shfl_xor_sync(0xffffffffu, s2, off);
    }
    if (lane == 0) { ss[warp] = s; sq[warp] = s2; }
    __syncthreads();
    if (threadIdx.x == 0) {
#pragma unroll
        for (int w = 1; w < 8; w++) { s += ss[w]; s2 += sq[w]; }
        atomicAdd(&g_sum[c], s);
        atomicAdd(&g_sumsq[c], s2);
    }
}

// -------------------- finalize stats --------------------
__global__ void k_stats() {
    int c = threadIdx.x;
    if (c < BC) {
        double mean = g_sum[c] / (double)NPIX;
        double var  = g_sumsq[c] / (double)NPIX - mean * mean;
        g_mean[c]   = (float)mean;
        g_invstd[c] = (float)(1.0 / sqrt(var + 1e-5));
    }
}

// -------------------- normalize in place --------------------
__global__ void k_norm(float* __restrict__ out) {
    int c = blockIdx.y;
    int o = c * NPIX + blockIdx.x * blockDim.x + threadIdx.x;
    out[o] = (out[o] - g_mean[c]) * g_invstd[c];
}

extern "C" void kernel_launch(void* const* d_in, const int* in_sizes, int n_in,
                              void* d_out, int out_size) {
    const float* img = (const float*)d_in[0];
    float* out = (float*)d_out;

    k_init<<<1, 32>>>();
    k_imgmax<<<dim3(64, BC), 256>>>(img);
    k_sobel<<<dim3(WW / 32, HH / 8, BC), dim3(32, 8)>>>(img);
    k_iter<<<dim3(16, 16, BC), dim3(32, 8)>>>(0);  // A -> B
    k_iter<<<dim3(16, 16, BC), dim3(32, 8)>>>(1);  // B -> A
    k_iter<<<dim3(16, 16, BC), dim3(32, 8)>>>(0);  // A -> B
    k_angle<<<dim3(NPIX / 256, BC), 256>>>(out);
    k_stats<<<1, 32>>>();
    k_norm<<<dim3(NPIX / 256, BC), 256>>>(out);
}

// round 3
// speedup vs baseline: 1.1778x; 1.1778x over previous
#include <cuda_runtime.h>

#define HH 512
#define WW 512
#define BC 6
#define NPIX (HH * WW)

// ---- static device scratch (no runtime allocation allowed) ----
__device__ float g_gmag[BC * NPIX];
__device__ float g_xnA[BC * NPIX];
__device__ float g_ynA[BC * NPIX];
__device__ float g_xnB[BC * NPIX];
__device__ float g_ynB[BC * NPIX];
__device__ int    g_imgmax[BC];
__device__ int    g_gmax[BC];
__device__ double g_sum[BC];
__device__ double g_sumsq[BC];
__device__ float  g_mean[BC];
__device__ float  g_invstd[BC];

__device__ __forceinline__ int refl(int i, int n) {
    if (i < 0) i = -i;
    if (i >= n) i = 2 * (n - 1) - i;
    return i;
}

__device__ __forceinline__ float tanh_fast(float x) {
    float y;
    asm("tanh.approx.f32 %0, %1;" : "=f"(y) : "f"(x));
    return y;
}

// -------------------- init --------------------
__global__ void k_init() {
    int i = threadIdx.x;
    if (i < BC) {
        g_imgmax[i] = 0;
        g_gmax[i]   = 0;
        g_sum[i]    = 0.0;
        g_sumsq[i]  = 0.0;
    }
}

// -------------------- per-channel max of img --------------------
__global__ void k_imgmax(const float* __restrict__ img) {
    int c = blockIdx.y;
    const float* p = img + c * NPIX;
    float m = 0.f;
    for (int i = blockIdx.x * blockDim.x + threadIdx.x; i < NPIX;
         i += gridDim.x * blockDim.x)
        m = fmaxf(m, p[i]);
    __shared__ float sm[8];
    int lane = threadIdx.x & 31, warp = threadIdx.x >> 5;
#pragma unroll
    for (int o = 16; o; o >>= 1) m = fmaxf(m, __shfl_xor_sync(0xffffffffu, m, o));
    if (lane == 0) sm[warp] = m;
    __syncthreads();
    if (threadIdx.x == 0) {
#pragma unroll
        for (int i = 1; i < 8; i++) m = fmaxf(m, sm[i]);
        atomicMax(&g_imgmax[c], __float_as_int(m));
    }
}

// -------------------- Sobel + rotate + gmag max --------------------
__global__ void k_sobel(const float* __restrict__ img) {
    int c = blockIdx.z;
    const float* p = img + c * NPIX;
    int x = blockIdx.x * 32 + threadIdx.x;
    int y = blockIdx.y * 8 + threadIdx.y;
    float inv = 1.0f / __int_as_float(g_imgmax[c]);

    float a[3][3];
#pragma unroll
    for (int j = 0; j < 3; j++)
#pragma unroll
        for (int i = 0; i < 3; i++) {
            int yy = y + j - 1, xx = x + i - 1;
            a[j][i] = ((unsigned)yy < HH && (unsigned)xx < WW) ? p[yy * WW + xx] : 0.f;
        }
    float gx = (a[0][2] - a[0][0]) + 2.f * (a[1][2] - a[1][0]) + (a[2][2] - a[2][0]);
    float gy = (a[2][0] - a[0][0]) + 2.f * (a[2][1] - a[0][1]) + (a[2][2] - a[0][2]);
    gx = fmaxf(gx * inv, 1e-12f);
    gy = fmaxf(gy * inv, 1e-12f);

    float gm = sqrtf(fmaf(gx, gx, gy * gy));
    float invg = 1.0f / gm;
    float x0 = gx * invg, y0 = gy * invg;
    const float ct = -4.3711388e-08f, st = 1.0f;
    float xn = x0 * ct - y0 * st;
    float yn = y0 * ct + x0 * st;

    int o = c * NPIX + y * WW + x;
    g_gmag[o] = gm;
    g_xnA[o]  = xn;
    g_ynA[o]  = yn;

    __shared__ float sm[8];
    int tid = threadIdx.y * 32 + threadIdx.x;
    int lane = tid & 31, warp = tid >> 5;
    float m = gm;
#pragma unroll
    for (int off = 16; off; off >>= 1) m = fmaxf(m, __shfl_xor_sync(0xffffffffu, m, off));
    if (lane == 0) sm[warp] = m;
    __syncthreads();
    if (tid == 0) {
#pragma unroll
        for (int i = 1; i < 8; i++) m = fmaxf(m, sm[i]);
        atomicMax(&g_gmax[c], __float_as_int(m));
    }
}

// -------------------- ETF iteration --------------------
// sel==0: read A write B ; sel==1: read B write A
// 32x32 tile, 32x8 threads, each thread computes 4 CONSECUTIVE rows so the
// four overlapping 5-row windows share shared-memory row loads (8 rows total).
__global__ void __launch_bounds__(256) k_iter(int sel) {
    __shared__ float4 s[36][36];   // (gnorm, xn, yn, pad) packed -> 1 LDS.128/neighbor

    int c = blockIdx.z;
    const float* gm = g_gmag + c * NPIX;
    const float* xi = (sel ? g_xnB : g_xnA) + c * NPIX;
    const float* yi = (sel ? g_ynB : g_ynA) + c * NPIX;
    float* xo = (sel ? g_xnA : g_xnB) + c * NPIX;
    float* yo = (sel ? g_ynA : g_ynB) + c * NPIX;

    float ginv = 1.0f / __int_as_float(g_gmax[c]);

    int bx0 = blockIdx.x * 32 - 2;
    int by0 = blockIdx.y * 32 - 2;
    int tid = threadIdx.y * 32 + threadIdx.x;

    for (int i = tid; i < 36 * 36; i += 256) {
        int ly = i / 36, lx = i - ly * 36;
        int gy = refl(by0 + ly, HH);
        int gx = refl(bx0 + lx, WW);
        int o = gy * WW + gx;
        s[ly][lx] = make_float4(gm[o] * ginv, xi[o], yi[o], 0.f);
    }
    __syncthreads();

    int tx = threadIdx.x;
    int row0 = threadIdx.y * 4;           // output-relative first row for this thread
    int px = blockIdx.x * 32 + tx;

    float gc[4], xc[4], yc[4], xr[4], yr[4];
#pragma unroll
    for (int k = 0; k < 4; k++) {
        float4 v = s[row0 + 2 + k][tx + 2];
        gc[k] = v.x; xc[k] = v.y; yc[k] = v.z;
        xr[k] = 0.f; yr[k] = 0.f;
    }

#pragma unroll
    for (int r = 0; r < 8; r++) {
        float4 v[5];
#pragma unroll
        for (int dx = 0; dx < 5; dx++) v[dx] = s[row0 + r][tx + dx];
#pragma unroll
        for (int k = 0; k < 4; k++) {
            if (r >= k && r <= k + 4) {   // static predicate, fully unrolled
#pragma unroll
                for (int dx = 0; dx < 5; dx++) {
                    float gn = v[dx].x, xnb = v[dx].y, ynb = v[dx].z;
                    float d  = gn - gc[k];
                    float wm = fmaf(0.5f, tanh_fast(d), 0.5f);  // 0.5*(1+tanh)
                    float dot = fmaf(xc[k], xnb, yc[k] * ynb);
                    float t   = (gn * wm) * dot;
                    xr[k] = fmaf(xnb, t, xr[k]);
                    yr[k] = fmaf(ynb, t, yr[k]);
                }
            }
        }
    }

#pragma unroll
    for (int k = 0; k < 4; k++) {
        float invm = rsqrtf(fmaf(xr[k], xr[k], yr[k] * yr[k]));
        int py = blockIdx.y * 32 + row0 + k;
        int o = py * WW + px;
        xo[o] = xr[k] * invm;
        yo[o] = yr[k] * invm;
    }
}

// -------------------- angle + per-channel sum/sumsq --------------------
__global__ void k_angle(float* __restrict__ out) {
    int c = blockIdx.y;
    int i = blockIdx.x * blockDim.x + threadIdx.x;
    int o = c * NPIX + i;
    float xn = g_xnB[o], yn = g_ynB[o];
    float ang = atanf(__fdividef(-yn, xn));
    float a = (180.0f * ang) / 3.14159274101257324f;
    out[o] = a;

    double s  = (double)a;
    double s2 = (double)a * (double)a;
    __shared__ double ss[8], sq[8];
    int lane = threadIdx.x & 31, warp = threadIdx.x >> 5;
#pragma unroll
    for (int off = 16; off; off >>= 1) {
        s  += __shfl_xor_sync(0xffffffffu, s, off);
        s2 += __shfl_xor_sync(0xffffffffu, s2, off);
    }
    if (lane == 0) { ss[warp] = s; sq[warp] = s2; }
    __syncthreads();
    if (threadIdx.x == 0) {
#pragma unroll
        for (int w = 1; w < 8; w++) { s += ss[w]; s2 += sq[w]; }
        atomicAdd(&g_sum[c], s);
        atomicAdd(&g_sumsq[c], s2);
    }
}

// -------------------- finalize stats --------------------
__global__ void k_stats() {
    int c = threadIdx.x;
    if (c < BC) {
        double mean = g_sum[c] / (double)NPIX;
        double var  = g_sumsq[c] / (double)NPIX - mean * mean;
        g_mean[c]   = (float)mean;
        g_invstd[c] = (float)(1.0 / sqrt(var + 1e-5));
    }
}

// -------------------- normalize in place --------------------
__global__ void k_norm(float* __restrict__ out) {
    int c = blockIdx.y;
    int o = c * NPIX + blockIdx.x * blockDim.x + threadIdx.x;
    out[o] = (out[o] - g_mean[c]) * g_invstd[c];
}

extern "C" void kernel_launch(void* const* d_in, const int* in_sizes, int n_in,
                              void* d_out, int out_size) {
    const float* img = (const float*)d_in[0];
    float* out = (float*)d_out;

    k_init<<<1, 32>>>();
    k_imgmax<<<dim3(64, BC), 256>>>(img);
    k_sobel<<<dim3(WW / 32, HH / 8, BC), dim3(32, 8)>>>(img);
    k_iter<<<dim3(16, 16, BC), dim3(32, 8)>>>(0);  // A -> B
    k_iter<<<dim3(16, 16, BC), dim3(32, 8)>>>(1);  // B -> A
    k_iter<<<dim3(16, 16, BC), dim3(32, 8)>>>(0);  // A -> B
    k_angle<<<dim3(NPIX / 256, BC), 256>>>(out);
    k_stats<<<1, 32>>>();
    k_norm<<<dim3(NPIX / 256, BC), 256>>>(out);
}

// round 4
// speedup vs baseline: 1.2337x; 1.0475x over previous
#include <cuda_runtime.h>

#define HH 512
#define WW 512
#define BC 6
#define NPIX (HH * WW)

// ---- static device scratch (no runtime allocation allowed) ----
__device__ float g_gmag[BC * NPIX];
__device__ float g_xnA[BC * NPIX];
__device__ float g_ynA[BC * NPIX];
__device__ float g_xnB[BC * NPIX];
__device__ float g_ynB[BC * NPIX];
__device__ int    g_gmax[BC];
__device__ double g_sum[BC];
__device__ double g_sumsq[BC];

__device__ __forceinline__ int refl(int i, int n) {
    if (i < 0) i = -i;
    if (i >= n) i = 2 * (n - 1) - i;
    return i;
}

__device__ __forceinline__ float tanh_fast(float x) {
    float y;
    asm("tanh.approx.f32 %0, %1;" : "=f"(y) : "f"(x));
    return y;
}

// -------------------- init --------------------
__global__ void k_init() {
    int i = threadIdx.x;
    if (i < BC) {
        g_gmax[i]  = 0;
        g_sum[i]   = 0.0;
        g_sumsq[i] = 0.0;
    }
}

// -------------------- Sobel + rotate + gmag max --------------------
// imgmax normalization dropped: gnorm/xn/yn are invariant to a uniform input
// scale (imgmax ~= 1) except at the 1e-12 clamp, where the difference
// saturates out in atan at the ~1e-12 level.
__global__ void k_sobel(const float* __restrict__ img) {
    int c = blockIdx.z;
    const float* p = img + c * NPIX;
    int x = blockIdx.x * 32 + threadIdx.x;
    int y = blockIdx.y * 8 + threadIdx.y;

    float a[3][3];
#pragma unroll
    for (int j = 0; j < 3; j++)
#pragma unroll
        for (int i = 0; i < 3; i++) {
            int yy = y + j - 1, xx = x + i - 1;
            a[j][i] = ((unsigned)yy < HH && (unsigned)xx < WW) ? p[yy * WW + xx] : 0.f;
        }
    float gx = (a[0][2] - a[0][0]) + 2.f * (a[1][2] - a[1][0]) + (a[2][2] - a[2][0]);
    float gy = (a[2][0] - a[0][0]) + 2.f * (a[2][1] - a[0][1]) + (a[2][2] - a[0][2]);
    gx = fmaxf(gx, 1e-12f);
    gy = fmaxf(gy, 1e-12f);

    float gm = sqrtf(fmaf(gx, gx, gy * gy));
    float invg = 1.0f / gm;
    float x0 = gx * invg, y0 = gy * invg;
    // rotation by fp32(pi/2): cos = -4.3711388e-8, sin = 1.0
    const float ct = -4.3711388e-08f, st = 1.0f;
    float xn = x0 * ct - y0 * st;
    float yn = y0 * ct + x0 * st;

    int o = c * NPIX + y * WW + x;
    g_gmag[o] = gm;
    g_xnA[o]  = xn;
    g_ynA[o]  = yn;

    __shared__ float sm[8];
    int tid = threadIdx.y * 32 + threadIdx.x;
    int lane = tid & 31, warp = tid >> 5;
    float m = gm;
#pragma unroll
    for (int off = 16; off; off >>= 1) m = fmaxf(m, __shfl_xor_sync(0xffffffffu, m, off));
    if (lane == 0) sm[warp] = m;
    __syncthreads();
    if (tid == 0) {
#pragma unroll
        for (int i = 1; i < 8; i++) m = fmaxf(m, sm[i]);
        atomicMax(&g_gmax[c], __float_as_int(m));
    }
}

// -------------------- ETF iteration --------------------
// sel==0: read A write B ; sel==1: read B write A
// 32x32 tile, 32x8 threads, 4 consecutive rows per thread.
// Per neighbor: 6 fma-pipe ops + 1 MUFU (tanh). The 0.5 in Wm is dropped
// (uniform positive per-center scale cancels in the final normalization) and
// gn*xn, gn*yn are precomputed into the shared tile.
__global__ void __launch_bounds__(256) k_iter(int sel) {
    __shared__ float4 sN[36][36];   // (xn, yn, gn*xn, gn*yn)
    __shared__ float  sG[36][36];   // gnorm

    int c = blockIdx.z;
    const float* gm = g_gmag + c * NPIX;
    const float* xi = (sel ? g_xnB : g_xnA) + c * NPIX;
    const float* yi = (sel ? g_ynB : g_ynA) + c * NPIX;
    float* xo = (sel ? g_xnA : g_xnB) + c * NPIX;
    float* yo = (sel ? g_ynA : g_ynB) + c * NPIX;

    float ginv = 1.0f / __int_as_float(g_gmax[c]);

    int bx0 = blockIdx.x * 32 - 2;
    int by0 = blockIdx.y * 32 - 2;
    int tid = threadIdx.y * 32 + threadIdx.x;

    for (int i = tid; i < 36 * 36; i += 256) {
        int ly = i / 36, lx = i - ly * 36;
        int gy = refl(by0 + ly, HH);
        int gx = refl(bx0 + lx, WW);
        int o = gy * WW + gx;
        float gn = gm[o] * ginv;
        float xv = xi[o], yv = yi[o];
        sN[ly][lx] = make_float4(xv, yv, gn * xv, gn * yv);
        sG[ly][lx] = gn;
    }
    __syncthreads();

    int tx = threadIdx.x;
    int row0 = threadIdx.y * 4;
    int px = blockIdx.x * 32 + tx;

    float gc[4], xc[4], yc[4], xr[4], yr[4];
#pragma unroll
    for (int k = 0; k < 4; k++) {
        float4 v = sN[row0 + 2 + k][tx + 2];
        gc[k] = sG[row0 + 2 + k][tx + 2];
        xc[k] = v.x; yc[k] = v.y;
        xr[k] = 0.f; yr[k] = 0.f;
    }

#pragma unroll
    for (int r = 0; r < 8; r++) {
        float4 n5[5];
        float  g5[5];
#pragma unroll
        for (int dx = 0; dx < 5; dx++) {
            n5[dx] = sN[row0 + r][tx + dx];
            g5[dx] = sG[row0 + r][tx + dx];
        }
#pragma unroll
        for (int k = 0; k < 4; k++) {
            if (r >= k && r <= k + 4) {    // static predicate, fully unrolled
#pragma unroll
                for (int dx = 0; dx < 5; dx++) {
                    float th  = tanh_fast(g5[dx] - gc[k]);
                    float dot = fmaf(xc[k], n5[dx].x, yc[k] * n5[dx].y);
                    float u   = fmaf(th, dot, dot);      // (1+tanh)*dot
                    xr[k] = fmaf(n5[dx].z, u, xr[k]);    // gn*xn * u
                    yr[k] = fmaf(n5[dx].w, u, yr[k]);    // gn*yn * u
                }
            }
        }
    }

#pragma unroll
    for (int k = 0; k < 4; k++) {
        float invm = rsqrtf(fmaf(xr[k], xr[k], yr[k] * yr[k]));
        int py = blockIdx.y * 32 + row0 + k;
        int o = py * WW + px;
        xo[o] = xr[k] * invm;
        yo[o] = yr[k] * invm;
    }
}

// -------------------- angle + per-channel sum/sumsq --------------------
__global__ void k_angle(float* __restrict__ out) {
    int c = blockIdx.y;
    int i = blockIdx.x * blockDim.x + threadIdx.x;
    int o = c * NPIX + i;
    float xn = g_xnB[o], yn = g_ynB[o];
    float ang = atanf(__fdividef(-yn, xn));
    float a = (180.0f * ang) / 3.14159274101257324f;
    out[o] = a;

    double s  = (double)a;
    double s2 = (double)a * (double)a;
    __shared__ double ss[8], sq[8];
    int lane = threadIdx.x & 31, warp = threadIdx.x >> 5;
#pragma unroll
    for (int off = 16; off; off >>= 1) {
        s  += __shfl_xor_sync(0xffffffffu, s, off);
        s2 += __shfl_xor_sync(0xffffffffu, s2, off);
    }
    if (lane == 0) { ss[warp] = s; sq[warp] = s2; }
    __syncthreads();
    if (threadIdx.x == 0) {
#pragma unroll
        for (int w = 1; w < 8; w++) { s += ss[w]; s2 += sq[w]; }
        atomicAdd(&g_sum[c], s);
        atomicAdd(&g_sumsq[c], s2);
    }
}

// -------------------- normalize (stats computed per-block) --------------------
__global__ void k_norm(float* __restrict__ out) {
    __shared__ float smu, sinv;
    int c = blockIdx.y;
    if (threadIdx.x == 0) {
        double mean = g_sum[c] / (double)NPIX;
        double var  = g_sumsq[c] / (double)NPIX - mean * mean;
        smu  = (float)mean;
        sinv = (float)(1.0 / sqrt(var + 1e-5));
    }
    __syncthreads();
    int o = c * NPIX + blockIdx.x * blockDim.x + threadIdx.x;
    out[o] = (out[o] - smu) * sinv;
}

extern "C" void kernel_launch(void* const* d_in, const int* in_sizes, int n_in,
                              void* d_out, int out_size) {
    const float* img = (const float*)d_in[0];
    float* out = (float*)d_out;

    k_init<<<1, 32>>>();
    k_sobel<<<dim3(WW / 32, HH / 8, BC), dim3(32, 8)>>>(img);
    k_iter<<<dim3(16, 16, BC), dim3(32, 8)>>>(0);  // A -> B
    k_iter<<<dim3(16, 16, BC), dim3(32, 8)>>>(1);  // B -> A
    k_iter<<<dim3(16, 16, BC), dim3(32, 8)>>>(0);  // A -> B
    k_angle<<<dim3(NPIX / 256, BC), 256>>>(out);
    k_norm<<<dim3(NPIX / 256, BC), 256>>>(out);
}

// round 5
// speedup vs baseline: 1.7541x; 1.4218x over previous
#include <cuda_runtime.h>

#define HH 512
#define WW 512
#define BC 6
#define NPIX (HH * WW)

// ---- static device scratch (no runtime allocation allowed) ----
// State recycling: all counters start zero (CUDA zero-init) and every replay
// re-zeros them at a point that is ordered before their next use:
//   g_sum/g_sumsq : zeroed in k_sobel (before k_iter3's atomics)
//   g_gmax        : zeroed in k_norm  (after its last reader, before next
//                   replay's k_sobel atomics)
__device__ float g_gmag[BC * NPIX];
__device__ float g_xnA[BC * NPIX];
__device__ float g_ynA[BC * NPIX];
__device__ float g_xnB[BC * NPIX];
__device__ float g_ynB[BC * NPIX];
__device__ int    g_gmax[BC];
__device__ double g_sum[BC];
__device__ double g_sumsq[BC];

__device__ __forceinline__ int refl(int i, int n) {
    if (i < 0) i = -i;
    if (i >= n) i = 2 * (n - 1) - i;
    return i;
}

__device__ __forceinline__ float tanh_fast(float x) {
    float y;
    asm("tanh.approx.f32 %0, %1;" : "=f"(y) : "f"(x));
    return y;
}

// Branchless Cephes-style atan, max err ~2e-7 rad.
__device__ __forceinline__ float atan_fast(float x) {
    float ax = fabsf(x);
    bool big = ax > 2.414213562f;     // tan(3pi/8)
    bool mid = ax > 0.4142135624f;    // tan(pi/8)
    float num = big ? -1.0f : ax - 1.0f;
    float den = big ? ax : ax + 1.0f;
    float r = mid ? __fdividef(num, den) : ax;
    float base = big ? 1.57079632679f : (mid ? 0.78539816340f : 0.0f);
    float z = r * r;
    float p = fmaf(fmaf(fmaf(8.05374449538e-2f, z, -1.38776856032e-1f), z,
                        1.99777106478e-1f), z, -3.33329491539e-1f);
    float res = base + fmaf(p * z, r, r);
    return copysignf(res, x);
}

// -------------------- Sobel + rotate + gmag max --------------------
__global__ void k_sobel(const float* __restrict__ img) {
    int c = blockIdx.z;
    const float* p = img + c * NPIX;
    int x = blockIdx.x * 32 + threadIdx.x;
    int y = blockIdx.y * 8 + threadIdx.y;
    int tid = threadIdx.y * 32 + threadIdx.x;

    // zero the instance-norm accumulators for this replay (ordered before
    // k_iter3's atomics by stream order)
    if (blockIdx.x == 0 && blockIdx.y == 0 && tid == 0) {
        g_sum[c] = 0.0;
        g_sumsq[c] = 0.0;
    }

    float a[3][3];
#pragma unroll
    for (int j = 0; j < 3; j++)
#pragma unroll
        for (int i = 0; i < 3; i++) {
            int yy = y + j - 1, xx = x + i - 1;
            a[j][i] = ((unsigned)yy < HH && (unsigned)xx < WW) ? p[yy * WW + xx] : 0.f;
        }
    float gx = (a[0][2] - a[0][0]) + 2.f * (a[1][2] - a[1][0]) + (a[2][2] - a[2][0]);
    float gy = (a[2][0] - a[0][0]) + 2.f * (a[2][1] - a[0][1]) + (a[2][2] - a[0][2]);
    // uniform input scale (imgmax) is dropped: results are scale-invariant
    gx = fmaxf(gx, 1e-12f);
    gy = fmaxf(gy, 1e-12f);

    float gm = sqrtf(fmaf(gx, gx, gy * gy));
    float invg = 1.0f / gm;
    float x0 = gx * invg, y0 = gy * invg;
    const float ct = -4.3711388e-08f, st = 1.0f;  // fp32 cos/sin(pi/2)
    float xn = x0 * ct - y0 * st;
    float yn = y0 * ct + x0 * st;

    int o = c * NPIX + y * WW + x;
    g_gmag[o] = gm;
    g_xnA[o]  = xn;
    g_ynA[o]  = yn;

    __shared__ float sm[8];
    int lane = tid & 31, warp = tid >> 5;
    float m = gm;
#pragma unroll
    for (int off = 16; off; off >>= 1) m = fmaxf(m, __shfl_xor_sync(0xffffffffu, m, off));
    if (lane == 0) sm[warp] = m;
    __syncthreads();
    if (tid == 0) {
#pragma unroll
        for (int i = 1; i < 8; i++) m = fmaxf(m, sm[i]);
        atomicMax(&g_gmax[c], __float_as_int(m));  // g_gmax zeroed by k_norm
    }
}

// -------------------- shared tile loader for ETF iterations --------------------
__device__ __forceinline__ void load_tile(
    float4 (*sN)[36], float (*sG)[36],
    const float* __restrict__ gm, const float* __restrict__ xi,
    const float* __restrict__ yi, float ginv, int bx0, int by0, int tid) {
    bool interior = (bx0 >= 0) && (by0 >= 0) && (bx0 + 36 <= WW) && (by0 + 36 <= HH);
    if (interior) {
        for (int i = tid; i < 36 * 36; i += 256) {
            int ly = i / 36, lx = i - ly * 36;
            int o = (by0 + ly) * WW + bx0 + lx;
            float gn = gm[o] * ginv;
            float xv = xi[o], yv = yi[o];
            sN[ly][lx] = make_float4(xv, yv, gn * xv, gn * yv);
            sG[ly][lx] = gn;
        }
    } else {
        for (int i = tid; i < 36 * 36; i += 256) {
            int ly = i / 36, lx = i - ly * 36;
            int o = refl(by0 + ly, HH) * WW + refl(bx0 + lx, WW);
            float gn = gm[o] * ginv;
            float xv = xi[o], yv = yi[o];
            sN[ly][lx] = make_float4(xv, yv, gn * xv, gn * yv);
            sG[ly][lx] = gn;
        }
    }
}

// core 5x5 weighted accumulation for 4 consecutive rows per thread
__device__ __forceinline__ void etf_core(
    float4 (*sN)[36], float (*sG)[36], int tx, int row0,
    float* xr, float* yr) {
    float gc[4], xc[4], yc[4];
#pragma unroll
    for (int k = 0; k < 4; k++) {
        float4 v = sN[row0 + 2 + k][tx + 2];
        gc[k] = sG[row0 + 2 + k][tx + 2];
        xc[k] = v.x; yc[k] = v.y;
        xr[k] = 0.f; yr[k] = 0.f;
    }
#pragma unroll
    for (int r = 0; r < 8; r++) {
        float4 n5[5];
        float  g5[5];
#pragma unroll
        for (int dx = 0; dx < 5; dx++) {
            n5[dx] = sN[row0 + r][tx + dx];
            g5[dx] = sG[row0 + r][tx + dx];
        }
#pragma unroll
        for (int k = 0; k < 4; k++) {
            if (r >= k && r <= k + 4) {
#pragma unroll
                for (int dx = 0; dx < 5; dx++) {
                    float th  = tanh_fast(g5[dx] - gc[k]);
                    float dot = fmaf(xc[k], n5[dx].x, yc[k] * n5[dx].y);
                    float u   = fmaf(th, dot, dot);      // (1+tanh)*dot
                    xr[k] = fmaf(n5[dx].z, u, xr[k]);
                    yr[k] = fmaf(n5[dx].w, u, yr[k]);
                }
            }
        }
    }
}

// -------------------- ETF iterations 1 & 2 --------------------
__global__ void __launch_bounds__(256) k_iter(int sel) {
    __shared__ float4 sN[36][36];
    __shared__ float  sG[36][36];

    int c = blockIdx.z;
    const float* gm = g_gmag + c * NPIX;
    const float* xi = (sel ? g_xnB : g_xnA) + c * NPIX;
    const float* yi = (sel ? g_ynB : g_ynA) + c * NPIX;
    float* xo = (sel ? g_xnA : g_xnB) + c * NPIX;
    float* yo = (sel ? g_ynA : g_ynB) + c * NPIX;

    float ginv = 1.0f / __int_as_float(g_gmax[c]);
    int bx0 = blockIdx.x * 32 - 2;
    int by0 = blockIdx.y * 32 - 2;
    int tid = threadIdx.y * 32 + threadIdx.x;

    load_tile(sN, sG, gm, xi, yi, ginv, bx0, by0, tid);
    __syncthreads();

    int tx = threadIdx.x;
    int row0 = threadIdx.y * 4;
    int px = blockIdx.x * 32 + tx;
    float xr[4], yr[4];
    etf_core(sN, sG, tx, row0, xr, yr);

#pragma unroll
    for (int k = 0; k < 4; k++) {
        float invm = rsqrtf(fmaf(xr[k], xr[k], yr[k] * yr[k]));
        int o = (blockIdx.y * 32 + row0 + k) * WW + px;
        xo[o] = xr[k] * invm;
        yo[o] = yr[k] * invm;
    }
}

// -------------------- ETF iteration 3 fused with angle + stats --------------------
__global__ void __launch_bounds__(256) k_iter3(float* __restrict__ out) {
    __shared__ float4 sN[36][36];
    __shared__ float  sG[36][36];

    int c = blockIdx.z;
    const float* gm = g_gmag + c * NPIX;
    const float* xi = g_xnA + c * NPIX;   // iter1: A->B, iter2: B->A, iter3 reads A
    const float* yi = g_ynA + c * NPIX;

    float ginv = 1.0f / __int_as_float(g_gmax[c]);
    int bx0 = blockIdx.x * 32 - 2;
    int by0 = blockIdx.y * 32 - 2;
    int tid = threadIdx.y * 32 + threadIdx.x;

    load_tile(sN, sG, gm, xi, yi, ginv, bx0, by0, tid);
    __syncthreads();

    int tx = threadIdx.x;
    int row0 = threadIdx.y * 4;
    int px = blockIdx.x * 32 + tx;
    float xr[4], yr[4];
    etf_core(sN, sG, tx, row0, xr, yr);

    double s = 0.0, s2 = 0.0;
#pragma unroll
    for (int k = 0; k < 4; k++) {
        // normalization cancels inside atan(-y/x); divide directly
        float t = __fdividef(-yr[k], xr[k]);
        float a = atan_fast(t) * 57.2957795131f;  // 180/pi
        int o = c * NPIX + (blockIdx.y * 32 + row0 + k) * WW + px;
        out[o] = a;
        s += (double)a;
        s2 += (double)a * (double)a;
    }

    __shared__ double ss[8], sq[8];
    int lane = tid & 31, warp = tid >> 5;
#pragma unroll
    for (int off = 16; off; off >>= 1) {
        s  += __shfl_xor_sync(0xffffffffu, s, off);
        s2 += __shfl_xor_sync(0xffffffffu, s2, off);
    }
    if (lane == 0) { ss[warp] = s; sq[warp] = s2; }
    __syncthreads();
    if (tid == 0) {
#pragma unroll
        for (int w = 1; w < 8; w++) { s += ss[w]; s2 += sq[w]; }
        atomicAdd(&g_sum[c], s);
        atomicAdd(&g_sumsq[c], s2);
    }
}

// -------------------- normalize + recycle state --------------------
__global__ void k_norm(float* __restrict__ out) {
    __shared__ float smu, sinv;
    int c = blockIdx.y;
    if (threadIdx.x == 0) {
        double mean = g_sum[c] / (double)NPIX;
        double var  = g_sumsq[c] / (double)NPIX - mean * mean;
        smu  = (float)mean;
        sinv = (float)(1.0 / sqrt(var + 1e-5));
        if (blockIdx.x == 0) g_gmax[c] = 0;   // recycle for next replay
    }
    __syncthreads();
    int o = c * NPIX + blockIdx.x * blockDim.x + threadIdx.x;
    out[o] = (out[o] - smu) * sinv;
}

extern "C" void kernel_launch(void* const* d_in, const int* in_sizes, int n_in,
                              void* d_out, int out_size) {
    const float* img = (const float*)d_in[0];
    float* out = (float*)d_out;

    k_sobel<<<dim3(WW / 32, HH / 8, BC), dim3(32, 8)>>>(img);
    k_iter<<<dim3(16, 16, BC), dim3(32, 8)>>>(0);   // A -> B
    k_iter<<<dim3(16, 16, BC), dim3(32, 8)>>>(1);   // B -> A
    k_iter3<<<dim3(16, 16, BC), dim3(32, 8)>>>(out);// A -> out (+stats)
    k_norm<<<dim3(NPIX / 256, BC), 256>>>(out);
}